// round 14
// baseline (speedup 1.0000x reference)
#include <cuda_runtime.h>
#include <math.h>
#include <stdint.h>

#define GX 200
#define GY 200
#define GZ 16
#define NVOX (GX*GY*GZ)
#define NCOL (GX*GY)          // 40000 xy columns
#define F_N 8
#define G_MAX 32768
#define CAP 128               // per-column entries (mean ~16)

__device__ int    g_count[NCOL];
__device__ float4 g_entries[NCOL * CAP];   // {e0, e1, e2, pack(gid | zmask<<15)}
__device__ float4 g_feats[G_MAX * 2];

__device__ __forceinline__ float ex2f(float x) {
    float r; asm("ex2.approx.f32 %0, %1;" : "=f"(r) : "f"(x)); return r;
}

// ---------- Pass 1: 8 lanes per gaussian (4 gaussians per warp) ----------
__global__ void gv_bin_kernel(const float* __restrict__ means,
                              const float* __restrict__ opac,
                              const float* __restrict__ cov,
                              const float* __restrict__ feat,
                              int G) {
    int g = (blockIdx.x * blockDim.x + threadIdx.x) >> 3;
    if (g >= G || g >= G_MAX) return;
    int sub = threadIdx.x & 7;

    const float lox = -40.f, loy = -40.f, loz = -1.f;
    const float hix =  40.f, hiy =  40.f, hiz =  5.4f;
    const float VOX = 0.4f;
    const float NHL2E = -0.5f * 1.4426950408889634f;   // -0.5 * log2(e)

    float mx = means[g*3 + 0];
    float my = means[g*3 + 1];
    float mz = means[g*3 + 2];
    const float* C = cov + (size_t)g * 9;
    float c00 = C[0], c01 = C[1], c02 = C[2];
    float c11 = C[4], c12 = C[5], c22 = C[8];

    // repack features (feat rows are 32B-aligned)
    const float4* fv = (const float4*)(feat + (size_t)g * F_N);
    if (sub == 0) g_feats[g*2 + 0] = fv[0];
    if (sub == 1) g_feats[g*2 + 1] = fv[1];

    float sx = sqrtf(c00), sy = sqrtf(c11), sz = sqrtf(c22);
    float blx = mx - 3.f*sx, bly = my - 3.f*sy, blz = mz - 3.f*sz;
    float bhx = mx + 3.f*sx, bhy = my + 3.f*sy, bhz = mz + 3.f*sz;

    bool valid = (bhx > lox) && (bhy > loy) && (bhz > loz) &&
                 (blx < hix) && (bly < hiy) && (blz < hiz);
    if (!valid) return;

    // symmetric 3x3 inverse
    float i00 = c11*c22 - c12*c12;
    float i01 = c02*c12 - c01*c22;
    float i02 = c01*c12 - c02*c11;
    float i11 = c00*c22 - c02*c02;
    float i12 = c01*c02 - c00*c12;
    float i22 = c00*c11 - c01*c01;
    float det = c00*i00 + c01*i01 + c02*i02;
    float rdet = 1.f / det;
    float a00 = i00*rdet, a01 = i01*rdet, a02 = i02*rdet;
    float a11 = i11*rdet, a12 = i12*rdet, a22 = i22*rdet;

    float blxc = fminf(fmaxf(blx, lox), hix);
    float blyc = fminf(fmaxf(bly, loy), hiy);
    float blzc = fminf(fmaxf(blz, loz), hiz);
    float bhxc = fminf(fmaxf(bhx, lox), hix);
    float bhyc = fminf(fmaxf(bhy, loy), hiy);
    float bhzc = fminf(fmaxf(bhz, loz), hiz);

    int ilox = min((int)((blxc - lox) / VOX), GX - 1);
    int iloy = min((int)((blyc - loy) / VOX), GY - 1);
    int iloz = min((int)((blzc - loz) / VOX), GZ - 1);
    int ihix = min((int)((bhxc - lox) / VOX), GX - 1);
    int ihiy = min((int)((bhyc - loy) / VOX), GY - 1);
    int ihiz = min((int)((bhzc - loz) / VOX), GZ - 1);

    int nx = ihix - ilox + 1;
    int ny = ihiy - iloy + 1;

    float op = opac[g];
    float l2op = (op > 0.f) ? log2f(op) : -127.f;

    unsigned zmask = (0xFFFFu << iloz) & (0xFFFFu >> (15 - ihiz));
    unsigned pk = (unsigned)g | (zmask << 15);

    int ncols = nx * ny;
    for (int p = sub; p < ncols; p += 8) {
        int ox = p / ny;
        int oy = p - ox * ny;
        int ix = ilox + ox;
        int iy = iloy + oy;
        float dx = ((float)ix + 0.5f) * VOX + lox - mx;
        float dy = ((float)iy + 0.5f) * VOX + loy - my;
        float cxy = a00*dx*dx + a11*dy*dy + 2.f*a01*dx*dy;
        float L   = a02*dx + a12*dy;
        // maha(wz) = cxy + 2L(wz-mz) + a22(wz-mz)^2 as quadratic in wz
        float q2 = a22;
        float q1 = 2.f*L - 2.f*a22*mz;
        float q0 = cxy - 2.f*L*mz + a22*mz*mz;
        float e2 = NHL2E * q2;
        float e1 = NHL2E * q1;
        float e0 = NHL2E * q0 + l2op;

        int col = ix * GY + iy;
        int pos = atomicAdd(&g_count[col], 1);
        if (pos < CAP)
            g_entries[col * CAP + pos] =
                make_float4(e0, e1, e2, __uint_as_float(pk));
    }
}

// ---------- Pass 2: 4 lanes per column, 4 z-voxels per thread ----------
__global__ void gv_gather_kernel(float* __restrict__ out) {
    int tid = blockIdx.x * blockDim.x + threadIdx.x;
    int col = tid >> 2;
    if (col >= NCOL) return;
    int zs = (tid & 3) << 2;           // z quad {zs..zs+3}

    const float loz = -1.f;
    const float VOX = 0.4f;
    float wz0 = ((float)zs + 0.5f) * VOX + loz;
    float wz1 = wz0 + VOX;
    float wz2 = wz1 + VOX;
    float wz3 = wz2 + VOX;

    int n = min(g_count[col], CAP);
    const float4* elist = g_entries + (size_t)col * CAP;

    float d0 = 0.f, d1 = 0.f, d2 = 0.f, d3 = 0.f;
    float A0[8] = {0,0,0,0,0,0,0,0};
    float A1[8] = {0,0,0,0,0,0,0,0};
    float A2[8] = {0,0,0,0,0,0,0,0};
    float A3[8] = {0,0,0,0,0,0,0,0};

    for (int e = 0; e < n; e++) {
        float4 q = elist[e];                 // broadcast across 4 z-lanes
        unsigned pk = __float_as_uint(q.w);
        unsigned m4 = (pk >> (15 + zs)) & 0xFu;
        if (!m4) continue;

        float ev0 = (m4 & 1u) ? ex2f(q.x + wz0 * (q.y + q.z * wz0)) : 0.f;
        float ev1 = (m4 & 2u) ? ex2f(q.x + wz1 * (q.y + q.z * wz1)) : 0.f;
        float ev2 = (m4 & 4u) ? ex2f(q.x + wz2 * (q.y + q.z * wz2)) : 0.f;
        float ev3 = (m4 & 8u) ? ex2f(q.x + wz3 * (q.y + q.z * wz3)) : 0.f;

        int gid = pk & 0x7FFF;
        float4 f0 = g_feats[gid*2 + 0];
        float4 f1 = g_feats[gid*2 + 1];
        d0 += ev0; d1 += ev1; d2 += ev2; d3 += ev3;
        A0[0] += ev0*f0.x; A0[1] += ev0*f0.y; A0[2] += ev0*f0.z; A0[3] += ev0*f0.w;
        A0[4] += ev0*f1.x; A0[5] += ev0*f1.y; A0[6] += ev0*f1.z; A0[7] += ev0*f1.w;
        A1[0] += ev1*f0.x; A1[1] += ev1*f0.y; A1[2] += ev1*f0.z; A1[3] += ev1*f0.w;
        A1[4] += ev1*f1.x; A1[5] += ev1*f1.y; A1[6] += ev1*f1.z; A1[7] += ev1*f1.w;
        A2[0] += ev2*f0.x; A2[1] += ev2*f0.y; A2[2] += ev2*f0.z; A2[3] += ev2*f0.w;
        A2[4] += ev2*f1.x; A2[5] += ev2*f1.y; A2[6] += ev2*f1.z; A2[7] += ev2*f1.w;
        A3[0] += ev3*f0.x; A3[1] += ev3*f0.y; A3[2] += ev3*f0.z; A3[3] += ev3*f0.w;
        A3[4] += ev3*f1.x; A3[5] += ev3*f1.y; A3[6] += ev3*f1.z; A3[7] += ev3*f1.w;
    }

    int vox = col * GZ + zs;
    *(float4*)(out + vox) = make_float4(d0, d1, d2, d3);

    float s0 = 1.f / fmaxf(d0, 1e-6f);
    float s1 = 1.f / fmaxf(d1, 1e-6f);
    float s2 = 1.f / fmaxf(d2, 1e-6f);
    float s3 = 1.f / fmaxf(d3, 1e-6f);
    float4* fp = (float4*)(out + NVOX) + (size_t)vox * 2;
    fp[0] = make_float4(A0[0]*s0, A0[1]*s0, A0[2]*s0, A0[3]*s0);
    fp[1] = make_float4(A0[4]*s0, A0[5]*s0, A0[6]*s0, A0[7]*s0);
    fp[2] = make_float4(A1[0]*s1, A1[1]*s1, A1[2]*s1, A1[3]*s1);
    fp[3] = make_float4(A1[4]*s1, A1[5]*s1, A1[6]*s1, A1[7]*s1);
    fp[4] = make_float4(A2[0]*s2, A2[1]*s2, A2[2]*s2, A2[3]*s2);
    fp[5] = make_float4(A2[4]*s2, A2[5]*s2, A2[6]*s2, A2[7]*s2);
    fp[6] = make_float4(A3[0]*s3, A3[1]*s3, A3[2]*s3, A3[3]*s3);
    fp[7] = make_float4(A3[4]*s3, A3[5]*s3, A3[6]*s3, A3[7]*s3);
}

extern "C" void kernel_launch(void* const* d_in, const int* in_sizes, int n_in,
                              void* d_out, int out_size) {
    const float* means = (const float*)d_in[0];   // (G,3)
    const float* opac  = (const float*)d_in[1];   // (G,1)
    const float* cov   = (const float*)d_in[2];   // (G,3,3)
    const float* feat  = (const float*)d_in[3];   // (G,8)
    float* out = (float*)d_out;                   // [640000 density | 5120000 feats]

    int G = in_sizes[0] / 3;

    void* cnt_ptr = nullptr;
    cudaGetSymbolAddress(&cnt_ptr, g_count);
    cudaMemsetAsync(cnt_ptr, 0, NCOL * sizeof(int));

    gv_bin_kernel<<<(G * 8 + 255) / 256, 256>>>(means, opac, cov, feat, G);

    int gthreads = NCOL * 4;   // 160,000
    gv_gather_kernel<<<(gthreads + 255) / 256, 256>>>(out);
}

// round 15
// speedup vs baseline: 1.2070x; 1.2070x over previous
#include <cuda_runtime.h>
#include <math.h>
#include <stdint.h>

#define GX 200
#define GY 200
#define GZ 16
#define NVOX (GX*GY*GZ)
#define NCOL (GX*GY)          // 40000 xy columns
#define F_N 8
#define G_MAX 32768
#define CAP 48                // per-column entries (mean ~16, 8-sigma headroom); 31MB -> L2-resident

__device__ int    g_count[NCOL];
__device__ float4 g_entries[NCOL * CAP + 1];   // +1 pad for safe next-entry prefetch
__device__ float4 g_feats[G_MAX * 2];

__device__ __forceinline__ float ex2f(float x) {
    float r; asm("ex2.approx.f32 %0, %1;" : "=f"(r) : "f"(x)); return r;
}

// ---------- Pass 1: 8 lanes per gaussian (4 gaussians per warp) ----------
__global__ void gv_bin_kernel(const float* __restrict__ means,
                              const float* __restrict__ opac,
                              const float* __restrict__ cov,
                              const float* __restrict__ feat,
                              int G) {
    int g = (blockIdx.x * blockDim.x + threadIdx.x) >> 3;
    if (g >= G || g >= G_MAX) return;
    int sub = threadIdx.x & 7;

    const float lox = -40.f, loy = -40.f, loz = -1.f;
    const float hix =  40.f, hiy =  40.f, hiz =  5.4f;
    const float VOX = 0.4f;
    const float NHL2E = -0.5f * 1.4426950408889634f;   // -0.5 * log2(e)

    float mx = means[g*3 + 0];
    float my = means[g*3 + 1];
    float mz = means[g*3 + 2];
    const float* C = cov + (size_t)g * 9;
    float c00 = C[0], c01 = C[1], c02 = C[2];
    float c11 = C[4], c12 = C[5], c22 = C[8];

    // repack features (feat rows are 32B-aligned)
    const float4* fv = (const float4*)(feat + (size_t)g * F_N);
    if (sub == 0) g_feats[g*2 + 0] = fv[0];
    if (sub == 1) g_feats[g*2 + 1] = fv[1];

    float sx = sqrtf(c00), sy = sqrtf(c11), sz = sqrtf(c22);
    float blx = mx - 3.f*sx, bly = my - 3.f*sy, blz = mz - 3.f*sz;
    float bhx = mx + 3.f*sx, bhy = my + 3.f*sy, bhz = mz + 3.f*sz;

    bool valid = (bhx > lox) && (bhy > loy) && (bhz > loz) &&
                 (blx < hix) && (bly < hiy) && (blz < hiz);
    if (!valid) return;

    // symmetric 3x3 inverse
    float i00 = c11*c22 - c12*c12;
    float i01 = c02*c12 - c01*c22;
    float i02 = c01*c12 - c02*c11;
    float i11 = c00*c22 - c02*c02;
    float i12 = c01*c02 - c00*c12;
    float i22 = c00*c11 - c01*c01;
    float det = c00*i00 + c01*i01 + c02*i02;
    float rdet = 1.f / det;
    float a00 = i00*rdet, a01 = i01*rdet, a02 = i02*rdet;
    float a11 = i11*rdet, a12 = i12*rdet, a22 = i22*rdet;

    float blxc = fminf(fmaxf(blx, lox), hix);
    float blyc = fminf(fmaxf(bly, loy), hiy);
    float blzc = fminf(fmaxf(blz, loz), hiz);
    float bhxc = fminf(fmaxf(bhx, lox), hix);
    float bhyc = fminf(fmaxf(bhy, loy), hiy);
    float bhzc = fminf(fmaxf(bhz, loz), hiz);

    int ilox = min((int)((blxc - lox) / VOX), GX - 1);
    int iloy = min((int)((blyc - loy) / VOX), GY - 1);
    int iloz = min((int)((blzc - loz) / VOX), GZ - 1);
    int ihix = min((int)((bhxc - lox) / VOX), GX - 1);
    int ihiy = min((int)((bhyc - loy) / VOX), GY - 1);
    int ihiz = min((int)((bhzc - loz) / VOX), GZ - 1);

    int nx = ihix - ilox + 1;
    int ny = ihiy - iloy + 1;

    float op = opac[g];
    float l2op = (op > 0.f) ? log2f(op) : -127.f;

    unsigned zmask = (0xFFFFu << iloz) & (0xFFFFu >> (15 - ihiz));
    unsigned pk = (unsigned)g | (zmask << 15);

    int ncols = nx * ny;
    for (int p = sub; p < ncols; p += 8) {
        int ox = p / ny;
        int oy = p - ox * ny;
        int ix = ilox + ox;
        int iy = iloy + oy;
        float dx = ((float)ix + 0.5f) * VOX + lox - mx;
        float dy = ((float)iy + 0.5f) * VOX + loy - my;
        float cxy = a00*dx*dx + a11*dy*dy + 2.f*a01*dx*dy;
        float L   = a02*dx + a12*dy;
        // maha(wz) = cxy + 2L(wz-mz) + a22(wz-mz)^2 as quadratic in wz
        float q2 = a22;
        float q1 = 2.f*L - 2.f*a22*mz;
        float q0 = cxy - 2.f*L*mz + a22*mz*mz;
        float e2 = NHL2E * q2;
        float e1 = NHL2E * q1;
        float e0 = NHL2E * q0 + l2op;

        int col = ix * GY + iy;
        int pos = atomicAdd(&g_count[col], 1);
        if (pos < CAP)
            g_entries[col * CAP + pos] =
                make_float4(e0, e1, e2, __uint_as_float(pk));
    }
}

// ---------- Pass 2: 8 lanes per column, 2 z-voxels per thread, prefetched ----------
__global__ void gv_gather_kernel(float* __restrict__ out) {
    int tid = blockIdx.x * blockDim.x + threadIdx.x;
    int col = tid >> 3;
    if (col >= NCOL) return;
    int zs = (tid & 7) << 1;           // z pair {zs, zs+1}

    const float loz = -1.f;
    const float VOX = 0.4f;
    float wz0 = ((float)zs + 0.5f) * VOX + loz;
    float wz1 = wz0 + VOX;

    int n = min(g_count[col], CAP);
    const float4* elist = g_entries + (size_t)col * CAP;

    float dens0 = 0.f, dens1 = 0.f;
    float p0 = 0.f, p1 = 0.f, p2 = 0.f, p3 = 0.f, p4 = 0.f, p5 = 0.f, p6 = 0.f, p7 = 0.f;
    float r0 = 0.f, r1 = 0.f, r2 = 0.f, r3 = 0.f, r4 = 0.f, r5 = 0.f, r6 = 0.f, r7 = 0.f;

    float4 q = elist[0];   // safe: array padded; unused if n==0
    for (int e = 0; e < n; e++) {
        float4 qn = elist[e + 1];        // prefetch next (pad makes it safe)
        unsigned pk = __float_as_uint(q.w);
        unsigned m2 = (pk >> (15 + zs)) & 3u;
        if (m2) {
            float ev0 = (m2 & 1u) ? ex2f(q.x + wz0 * (q.y + q.z * wz0)) : 0.f;
            float ev1 = (m2 & 2u) ? ex2f(q.x + wz1 * (q.y + q.z * wz1)) : 0.f;

            int gid = pk & 0x7FFF;
            float4 f0 = g_feats[gid*2 + 0];
            float4 f1 = g_feats[gid*2 + 1];
            dens0 += ev0; dens1 += ev1;
            p0 += ev0*f0.x; p1 += ev0*f0.y; p2 += ev0*f0.z; p3 += ev0*f0.w;
            p4 += ev0*f1.x; p5 += ev0*f1.y; p6 += ev0*f1.z; p7 += ev0*f1.w;
            r0 += ev1*f0.x; r1 += ev1*f0.y; r2 += ev1*f0.z; r3 += ev1*f0.w;
            r4 += ev1*f1.x; r5 += ev1*f1.y; r6 += ev1*f1.z; r7 += ev1*f1.w;
        }
        q = qn;
    }

    int vox = col * GZ + zs;
    out[vox]     = dens0;
    out[vox + 1] = dens1;
    float s0 = 1.f / fmaxf(dens0, 1e-6f);
    float s1 = 1.f / fmaxf(dens1, 1e-6f);
    float4* fp = (float4*)(out + NVOX) + (size_t)vox * 2;
    fp[0] = make_float4(p0*s0, p1*s0, p2*s0, p3*s0);
    fp[1] = make_float4(p4*s0, p5*s0, p6*s0, p7*s0);
    fp[2] = make_float4(r0*s1, r1*s1, r2*s1, r3*s1);
    fp[3] = make_float4(r4*s1, r5*s1, r6*s1, r7*s1);
}

extern "C" void kernel_launch(void* const* d_in, const int* in_sizes, int n_in,
                              void* d_out, int out_size) {
    const float* means = (const float*)d_in[0];   // (G,3)
    const float* opac  = (const float*)d_in[1];   // (G,1)
    const float* cov   = (const float*)d_in[2];   // (G,3,3)
    const float* feat  = (const float*)d_in[3];   // (G,8)
    float* out = (float*)d_out;                   // [640000 density | 5120000 feats]

    int G = in_sizes[0] / 3;

    void* cnt_ptr = nullptr;
    cudaGetSymbolAddress(&cnt_ptr, g_count);
    cudaMemsetAsync(cnt_ptr, 0, NCOL * sizeof(int));

    gv_bin_kernel<<<(G * 8 + 255) / 256, 256>>>(means, opac, cov, feat, G);

    int gthreads = NCOL * 8;   // 320,000
    gv_gather_kernel<<<(gthreads + 255) / 256, 256>>>(out);
}